// round 1
// baseline (speedup 1.0000x reference)
#include <cuda_runtime.h>

// Problem constants (fixed shapes from reference: B=16, K=64, H=96, W=96)
constexpr int B = 16;
constexpr int K = 64;
constexpr int H = 96;
constexpr int W = 96;
constexpr int IMG = H * W;                    // 9216 elements per (b,k) image
constexpr int NSTACK = B * K;                 // 1024 images per stack
constexpr long long NBIG = (long long)B * K * H * W;  // 9437184
constexpr int KP_ELEMS = B * 3 * K * 2;       // 6144 floats per keypoint tensor
constexpr int ZETA_ELEMS = B * K;             // 1024

constexpr int THREADS = 256;                  // 8 warps
constexpr int V4_PER_IMG = IMG / 4;           // 2304 float4
constexpr int ITERS = V4_PER_IMG / THREADS;   // 9

__device__ __forceinline__ float sigmoidf(float x) {
    // 1 / (1 + e^-x); __expf rel error ~1e-6, far under the 1e-3 gate
    return 1.0f / (1.0f + __expf(-x));
}

__global__ __launch_bounds__(THREADS, 8)
void fused_decode_kernel(const float* __restrict__ Rk,
                         const float* __restrict__ tfRk,
                         float* __restrict__ Dk_out,
                         float* __restrict__ tfDk_out,
                         float* __restrict__ kp_out,
                         float* __restrict__ tfkp_out,
                         float* __restrict__ zeta_out,
                         float* __restrict__ tfzeta_out)
{
    const int stack = blockIdx.x;             // 0..1023 = b*K + k
    const int which = blockIdx.y;             // 0 = Rk, 1 = tf_Rk

    const float* __restrict__ R  = (which == 0 ? Rk : tfRk) + (size_t)stack * IMG;
    float* __restrict__ D        = (which == 0 ? Dk_out : tfDk_out) + (size_t)stack * IMG;
    float* __restrict__ kp_base  = (which == 0 ? kp_out : tfkp_out);
    float* __restrict__ zeta_base = (which == 0 ? zeta_out : tfzeta_out);

    const int tid = threadIdx.x;

    const float4* __restrict__ R4 = reinterpret_cast<const float4*>(R);
    float4* __restrict__ D4 = reinterpret_cast<float4*>(D);

    float s0 = 0.0f;   // sum d
    float sx = 0.0f;   // sum d * x
    float sy = 0.0f;   // sum d * y

    // 96 floats per row = 24 float4 per row; a float4 never crosses a row.
#pragma unroll
    for (int it = 0; it < ITERS; ++it) {
        const int v = tid + it * THREADS;     // float4 index in [0, 2304)
        float4 r = R4[v];
        float4 d;
        d.x = sigmoidf(r.x);
        d.y = sigmoidf(r.y);
        d.z = sigmoidf(r.z);
        d.w = sigmoidf(r.w);
        D4[v] = d;

        const int e = v * 4;                  // element index
        const int h = e / W;
        const int w = e - h * W;              // column of d.x
        const float rowsum = (d.x + d.y) + (d.z + d.w);
        s0 += rowsum;
        sy += rowsum * (float)h;
        sx += d.x * (float)w + d.y * (float)(w + 1)
            + d.z * (float)(w + 2) + d.w * (float)(w + 3);
    }

    // ---- block reduction of (s0, sx, sy) ----
    const int lane = tid & 31;
    const int warp = tid >> 5;
#pragma unroll
    for (int o = 16; o > 0; o >>= 1) {
        s0 += __shfl_down_sync(0xffffffffu, s0, o);
        sx += __shfl_down_sync(0xffffffffu, sx, o);
        sy += __shfl_down_sync(0xffffffffu, sy, o);
    }
    __shared__ float sm0[8], smx[8], smy[8];
    if (lane == 0) { sm0[warp] = s0; smx[warp] = sx; smy[warp] = sy; }
    __syncthreads();

    if (tid == 0) {
        float z = 0.0f, fx = 0.0f, fy = 0.0f;
#pragma unroll
        for (int i = 0; i < 8; ++i) { z += sm0[i]; fx += smx[i]; fy += smy[i]; }

        // kp = round-half-even of moments / zeta (matches jnp.round)
        const float kx = rintf(fx / z);
        const float ky = rintf(fy / z);
        const int wi = (int)kx;
        const int hi = (int)ky;

        // d at rounded location: recompute sigmoid from the input (1 LDG)
        const float dloc = sigmoidf(R[hi * W + wi]);

        const int b = stack / K;
        const int k = stack - b * K;

        // keypoint layout [B, 3K, 2]: rows k (kp), K+k (kp1), 2K+k (kp2)
        float* kp  = kp_base + ((size_t)b * (3 * K) + k) * 2;
        float* kp1 = kp_base + ((size_t)b * (3 * K) + K + k) * 2;
        float* kp2 = kp_base + ((size_t)b * (3 * K) + 2 * K + k) * 2;
        kp[0]  = kx;
        kp[1]  = ky;
        kp1[0] = truncf(kx + kx * dloc);
        kp1[1] = truncf(ky + ky * dloc);
        kp2[0] = truncf(kx - kx * dloc);
        kp2[1] = truncf(ky - ky * dloc);

        zeta_base[stack] = z;
    }
}

extern "C" void kernel_launch(void* const* d_in, const int* in_sizes, int n_in,
                              void* d_out, int out_size)
{
    const float* Rk   = (const float*)d_in[0];
    const float* tfRk = (const float*)d_in[1];
    // d_in[2], d_in[3] are my_height / my_width scalars — shapes are fixed, ignored.

    float* out = (float*)d_out;
    // Output tuple layout, flattened in order:
    // Dk [B,K,H,W], tf_Dk [B,K,H,W], keypoint [B,3K,2], tf_keypoint [B,3K,2],
    // get_zeta [B,K], tf_get_zeta [B,K]
    float* Dk     = out;
    float* tfDk   = out + NBIG;
    float* kp     = out + 2 * NBIG;
    float* tfkp   = kp + KP_ELEMS;
    float* zeta   = tfkp + KP_ELEMS;
    float* tfzeta = zeta + ZETA_ELEMS;

    dim3 grid(NSTACK, 2);
    fused_decode_kernel<<<grid, THREADS>>>(Rk, tfRk, Dk, tfDk, kp, tfkp, zeta, tfzeta);
}